// round 1
// baseline (speedup 1.0000x reference)
#include <cuda_runtime.h>

#define NN   50000
#define EE   800000
#define RR   8
#define DIN  64
#define DHID 128
#define DOUT 64
#define EPSF 1e-5f

// ---------------- scratch (device globals; no allocation allowed) ----------------
__device__ float g_S1[NN * RR * DIN];          // [N, 8, 64] per-(dst,rel) sums of x[src]
__device__ int   g_cnt[NN * RR];               // per-(dst,rel) edge counts
__device__ float g_invcnt[NN * RR];            // 1/cnt (0 if cnt==0)
__device__ float g_h[NN * DHID];               // layer-1 output [N,128]
__device__ float g_C2[NN * 9 * DOUT];          // [N, 9, 64]: r<8 = h@W2[r]; r=8 = h@root2+bias2
__device__ float g_agg2[NN * DOUT];            // layer-2 aggregation [N,64]
__device__ int   g_is64;                       // edge index dtype flag

// ---------------- helpers ----------------
__device__ __forceinline__ int ld_idx(const void* p, int i, int is64) {
    if (is64) return (int)(((const long long*)p)[i]);
    return ((const int*)p)[i];
}

// Detect whether edge_index is int64 (odd 32-bit words of small int64s are 0).
__global__ void detect_kernel(const int* __restrict__ ei) {
    int all0 = 1;
    for (int k = 0; k < 32; k++)
        if (ei[2 * k + 1] != 0) all0 = 0;
    g_is64 = all0;
}

// Zero S1 (6.4M float4), cnt (100K int4), agg2 (800K float4) in one pass.
__global__ void zero_all_kernel() {
    int i = blockIdx.x * 256 + threadIdx.x;
    if (i < (NN * RR * DIN) / 4) ((float4*)g_S1)[i] = make_float4(0.f, 0.f, 0.f, 0.f);
    if (i < (NN * RR) / 4)       ((int4*)g_cnt)[i] = make_int4(0, 0, 0, 0);
    if (i < (NN * DOUT) / 4)     ((float4*)g_agg2)[i] = make_float4(0.f, 0.f, 0.f, 0.f);
}

__global__ void count_kernel(const void* __restrict__ ei, const void* __restrict__ et) {
    int e = blockIdx.x * 256 + threadIdx.x;
    if (e >= EE) return;
    int is64 = g_is64;
    int dst = ld_idx(ei, EE + e, is64);
    int r   = ld_idx(et, e, is64);
    atomicAdd(&g_cnt[dst * RR + r], 1);
}

__global__ void invcnt_kernel() {
    int i = blockIdx.x * 256 + threadIdx.x;
    if (i >= NN * RR) return;
    int c = g_cnt[i];
    g_invcnt[i] = (c > 0) ? (1.0f / (float)c) : 0.0f;
}

// Scatter layer 1: S1[dst, r, :] += x[src, :].  16 threads (float4 chunks) per edge.
__global__ void scatter1_kernel(const void* __restrict__ ei, const void* __restrict__ et,
                                const float* __restrict__ x) {
    int idx = blockIdx.x * 256 + threadIdx.x;   // EE*16 total
    int e = idx >> 4, c = idx & 15;
    int is64 = g_is64;
    int src = ld_idx(ei, e, is64);
    int dst = ld_idx(ei, EE + e, is64);
    int r   = ld_idx(et, e, is64);
    float4 v = ((const float4*)x)[src * 16 + c];
    atomicAdd((float4*)&g_S1[((size_t)dst * RR + r) * DIN + c * 4], v);
}

// GEMM1: h = leaky( [S1*invcnt | x] @ [W1 | root1] + bias1 ),  [N,576]x[576,128]
// BM=128, BN=128, BK=16, 256 threads, 8x8 microtile.
__global__ __launch_bounds__(256) void gemm1_kernel(
    const float* __restrict__ x, const float* __restrict__ W1,
    const float* __restrict__ root1, const float* __restrict__ bias1) {
    __shared__ float As[16][128];
    __shared__ float Bs[16][128];
    int n0 = blockIdx.x * 128;
    int tid = threadIdx.x;
    int tx = tid & 15, ty = tid >> 4;
    float acc[8][8];
#pragma unroll
    for (int i = 0; i < 8; i++)
#pragma unroll
        for (int j = 0; j < 8; j++) acc[i][j] = 0.f;

    for (int k0 = 0; k0 < 576; k0 += 16) {
        int r = k0 >> 6;  // relation of this k-tile (8 == root/x slice)
        // ---- load A tile (with invcnt scaling / x passthrough) ----
#pragma unroll
        for (int p0 = 0; p0 < 2; p0++) {
            int p = tid + p0 * 256;           // 0..511
            int m = p >> 2, kq = p & 3;
            int n = n0 + m;
            float4 v = make_float4(0.f, 0.f, 0.f, 0.f);
            float s = 0.f;
            if (n < NN) {
                if (k0 < 512) {
                    v = *(const float4*)(g_S1 + (size_t)n * 512 + k0 + kq * 4);
                    s = g_invcnt[n * 8 + r];
                } else {
                    v = *(const float4*)(x + (size_t)n * 64 + (k0 - 512) + kq * 4);
                    s = 1.f;
                }
            }
            int kb = kq * 4;
            As[kb + 0][m] = v.x * s;
            As[kb + 1][m] = v.y * s;
            As[kb + 2][m] = v.z * s;
            As[kb + 3][m] = v.w * s;
        }
        // ---- load B tile: W1 flat is exactly [512,128]; root1 is [64,128] ----
        const float* Bp = (k0 < 512) ? (W1 + (size_t)k0 * 128)
                                     : (root1 + (size_t)(k0 - 512) * 128);
#pragma unroll
        for (int p0 = 0; p0 < 2; p0++) {
            int p = tid + p0 * 256;
            int k = p >> 5, j4 = p & 31;
            *(float4*)&Bs[k][j4 * 4] = *(const float4*)(Bp + k * 128 + j4 * 4);
        }
        __syncthreads();
#pragma unroll
        for (int k = 0; k < 16; k++) {
            float a[8], b[8];
#pragma unroll
            for (int i = 0; i < 8; i++) a[i] = As[k][ty * 8 + i];
#pragma unroll
            for (int j = 0; j < 8; j++) b[j] = Bs[k][tx * 8 + j];
#pragma unroll
            for (int i = 0; i < 8; i++)
#pragma unroll
                for (int j = 0; j < 8; j++) acc[i][j] += a[i] * b[j];
        }
        __syncthreads();
    }
#pragma unroll
    for (int i = 0; i < 8; i++) {
        int n = n0 + ty * 8 + i;
        if (n >= NN) continue;
#pragma unroll
        for (int j = 0; j < 8; j++) {
            int col = tx * 8 + j;
            float c = acc[i][j] + bias1[col];
            c = (c >= 0.f) ? c : 0.2f * c;
            g_h[(size_t)n * 128 + col] = c;
        }
    }
}

// LayerNorm over 128 (in place on g_h), warp per row, two-pass for accuracy.
__global__ void ln1_kernel(const float* __restrict__ gamma, const float* __restrict__ beta) {
    int row = blockIdx.x * 8 + (threadIdx.x >> 5);
    if (row >= NN) return;
    int lane = threadIdx.x & 31;
    float4 v = ((const float4*)g_h)[(size_t)row * 32 + lane];
    float s = v.x + v.y + v.z + v.w;
#pragma unroll
    for (int o = 16; o; o >>= 1) s += __shfl_xor_sync(0xFFFFFFFFu, s, o);
    float mu = s * (1.f / 128.f);
    float dx = v.x - mu, dy = v.y - mu, dz = v.z - mu, dw = v.w - mu;
    float sq = dx * dx + dy * dy + dz * dz + dw * dw;
#pragma unroll
    for (int o = 16; o; o >>= 1) sq += __shfl_xor_sync(0xFFFFFFFFu, sq, o);
    float rstd = rsqrtf(sq * (1.f / 128.f) + EPSF);
    float4 g = ((const float4*)gamma)[lane];
    float4 b = ((const float4*)beta)[lane];
    v.x = dx * rstd * g.x + b.x;
    v.y = dy * rstd * g.y + b.y;
    v.z = dz * rstd * g.z + b.z;
    v.w = dw * rstd * g.w + b.w;
    ((float4*)g_h)[(size_t)row * 32 + lane] = v;
}

// GEMM2: C2[:, bx, :] = h @ (bx<8 ? W2[bx] : root2) (+bias2 on bx==8).
// BM=128, BN=64, BK=16, 256 threads, 8x4 microtile. grid = (391, 9)
__global__ __launch_bounds__(256) void gemm2_kernel(
    const float* __restrict__ W2, const float* __restrict__ root2,
    const float* __restrict__ bias2) {
    __shared__ float As[16][128];
    __shared__ float Bs[16][64];
    int n0 = blockIdx.x * 128;
    int bx = blockIdx.y;  // 0..8
    const float* Bbase = (bx < 8) ? (W2 + (size_t)bx * DHID * DOUT) : root2;  // [128,64]
    int tid = threadIdx.x;
    int tx = tid & 15, ty = tid >> 4;
    float acc[8][4];
#pragma unroll
    for (int i = 0; i < 8; i++)
#pragma unroll
        for (int j = 0; j < 4; j++) acc[i][j] = 0.f;

    for (int k0 = 0; k0 < 128; k0 += 16) {
#pragma unroll
        for (int p0 = 0; p0 < 2; p0++) {
            int p = tid + p0 * 256;
            int m = p >> 2, kq = p & 3;
            int n = n0 + m;
            float4 v = make_float4(0.f, 0.f, 0.f, 0.f);
            if (n < NN) v = *(const float4*)(g_h + (size_t)n * 128 + k0 + kq * 4);
            int kb = kq * 4;
            As[kb + 0][m] = v.x; As[kb + 1][m] = v.y;
            As[kb + 2][m] = v.z; As[kb + 3][m] = v.w;
        }
        {   // 16x64 = 256 float4
            int k = tid >> 4, j4 = tid & 15;
            *(float4*)&Bs[k][j4 * 4] = *(const float4*)(Bbase + (size_t)(k0 + k) * 64 + j4 * 4);
        }
        __syncthreads();
#pragma unroll
        for (int k = 0; k < 16; k++) {
            float a[8], b[4];
#pragma unroll
            for (int i = 0; i < 8; i++) a[i] = As[k][ty * 8 + i];
#pragma unroll
            for (int j = 0; j < 4; j++) b[j] = Bs[k][tx * 4 + j];
#pragma unroll
            for (int i = 0; i < 8; i++)
#pragma unroll
                for (int j = 0; j < 4; j++) acc[i][j] += a[i] * b[j];
        }
        __syncthreads();
    }
#pragma unroll
    for (int i = 0; i < 8; i++) {
        int n = n0 + ty * 8 + i;
        if (n >= NN) continue;
#pragma unroll
        for (int j = 0; j < 4; j++) {
            int jj = tx * 4 + j;
            float c = acc[i][j];
            if (bx == 8) c += bias2[jj];
            g_C2[(size_t)n * 576 + bx * 64 + jj] = c;
        }
    }
}

// Scatter layer 2: agg2[dst,:] += invcnt[dst,r] * C2[src, r, :]
__global__ void scatter2_kernel(const void* __restrict__ ei, const void* __restrict__ et) {
    int idx = blockIdx.x * 256 + threadIdx.x;  // EE*16
    int e = idx >> 4, c = idx & 15;
    int is64 = g_is64;
    int src = ld_idx(ei, e, is64);
    int dst = ld_idx(ei, EE + e, is64);
    int r   = ld_idx(et, e, is64);
    float norm = g_invcnt[dst * 8 + r];
    float4 v = *(const float4*)(g_C2 + (size_t)src * 576 + r * 64 + c * 4);
    v.x *= norm; v.y *= norm; v.z *= norm; v.w *= norm;
    atomicAdd((float4*)&g_agg2[(size_t)dst * 64 + c * 4], v);
}

// Final: out = LN(agg2 + C2[:,8,:]) over 64, warp per row.
__global__ void final_kernel(const float* __restrict__ gamma, const float* __restrict__ beta,
                             float* __restrict__ out) {
    int row = blockIdx.x * 8 + (threadIdx.x >> 5);
    if (row >= NN) return;
    int lane = threadIdx.x & 31;
    float2 a = ((const float2*)g_agg2)[(size_t)row * 32 + lane];
    float2 bse = *(const float2*)(g_C2 + (size_t)row * 576 + 512 + lane * 2);
    float vx = a.x + bse.x, vy = a.y + bse.y;
    float s = vx + vy;
#pragma unroll
    for (int o = 16; o; o >>= 1) s += __shfl_xor_sync(0xFFFFFFFFu, s, o);
    float mu = s * (1.f / 64.f);
    float dx = vx - mu, dy = vy - mu;
    float sq = dx * dx + dy * dy;
#pragma unroll
    for (int o = 16; o; o >>= 1) sq += __shfl_xor_sync(0xFFFFFFFFu, sq, o);
    float rstd = rsqrtf(sq * (1.f / 64.f) + EPSF);
    float2 g = ((const float2*)gamma)[lane];
    float2 b = ((const float2*)beta)[lane];
    float2 o2;
    o2.x = dx * rstd * g.x + b.x;
    o2.y = dy * rstd * g.y + b.y;
    ((float2*)out)[(size_t)row * 32 + lane] = o2;
}

// ---------------- launch ----------------
extern "C" void kernel_launch(void* const* d_in, const int* in_sizes, int n_in,
                              void* d_out, int out_size) {
    const float* x      = (const float*)d_in[0];
    const void*  ei     = d_in[1];
    const void*  et     = d_in[2];
    const float* W1     = (const float*)d_in[3];
    const float* root1  = (const float*)d_in[4];
    const float* bias1  = (const float*)d_in[5];
    const float* gamma1 = (const float*)d_in[6];
    const float* beta1  = (const float*)d_in[7];
    const float* W2     = (const float*)d_in[8];
    const float* root2  = (const float*)d_in[9];
    const float* bias2  = (const float*)d_in[10];
    const float* gamma2 = (const float*)d_in[11];
    const float* beta2  = (const float*)d_in[12];
    float* out = (float*)d_out;

    detect_kernel<<<1, 1>>>((const int*)ei);
    zero_all_kernel<<<(NN * RR * DIN / 4 + 255) / 256, 256>>>();
    count_kernel<<<(EE + 255) / 256, 256>>>(ei, et);
    invcnt_kernel<<<(NN * RR + 255) / 256, 256>>>();
    scatter1_kernel<<<EE * 16 / 256, 256>>>(ei, et, x);
    gemm1_kernel<<<(NN + 127) / 128, 256>>>(x, W1, root1, bias1);
    ln1_kernel<<<(NN + 7) / 8, 256>>>(gamma1, beta1);
    gemm2_kernel<<<dim3((NN + 127) / 128, 9), 256>>>(W2, root2, bias2);
    scatter2_kernel<<<EE * 16 / 256, 256>>>(ei, et);
    final_kernel<<<(NN + 7) / 8, 256>>>(gamma2, beta2, out);
}